// round 15
// baseline (speedup 1.0000x reference)
#include <cuda_runtime.h>
#include <math.h>
#include <stdint.h>

#define D_MODEL 1024
#define D_HID   256
#define N_EXP   64
#define NTOK    16384

// ---------------- packed fp32x2 helpers (FFMA2 path) ----------------
__device__ __forceinline__ unsigned long long pack2(float lo, float hi) {
    unsigned long long r;
    asm("mov.b64 %0, {%1, %2};" : "=l"(r) : "f"(lo), "f"(hi));
    return r;
}
__device__ __forceinline__ void ffma2(unsigned long long& d,
                                      unsigned long long a,
                                      unsigned long long b) {
    asm("fma.rn.f32x2 %0, %1, %2, %0;" : "+l"(d) : "l"(a), "l"(b));
}
__device__ __forceinline__ float2 unpack2(unsigned long long v) {
    float2 f;
    asm("mov.b64 {%0, %1}, %2;" : "=f"(f.x), "=f"(f.y) : "l"(v));
    return f;
}
__device__ __forceinline__ void cp16(uint32_t saddr, const void* gsrc) {
    asm volatile("cp.async.cg.shared.global [%0], [%1], 16;" :: "r"(saddr), "l"(gsrc) : "memory");
}
#define CP_COMMIT() asm volatile("cp.async.commit_group;" ::: "memory")
#define CP_WAIT0()  asm volatile("cp.async.wait_group 0;" ::: "memory")

__device__ __forceinline__ uint32_t smem_u32(const void* p) {
    uint32_t a;
    asm("{ .reg .u64 t; cvta.to.shared.u64 t, %1; cvt.u32.u64 %0, t; }" : "=r"(a) : "l"(p));
    return a;
}
// store {a,a,b,b} as one STS.128 (duplication with zero pack movs)
__device__ __forceinline__ void sts_dup4(uint32_t saddr, float a, float b) {
    asm volatile("st.shared.v4.f32 [%0], {%1, %1, %2, %2};"
                 :: "r"(saddr), "f"(a), "f"(b) : "memory");
}

// swizzled byte offset of col-pair cp in a dup-B row (16B per 2 cols)
__device__ __forceinline__ int boff(int cp) { return cp * 16 + (cp >> 3) * 16; }

// =============================================================================
// Fully fused gating network, pure fp32 (exact):
//   H = tanh(X@W1+b1) -> smem Ht[k][tok]; logits = H@W2+b2; top-2 softmax.
// CTA 256 thr, M=64 tokens (grid 256), N=256, BK=16, occ 2, 8x8 thread tile.
// Inner loop: A 2xLDS.128 (stride-68 rows, 16B-aligned) +
//             B(dup) 4xLDS.128 (contiguous 64B, aligned) + 32 FFMA2. Zero packs.
//
// Dynamic smem (bytes), temporally-disjoint overlays:
//  mainloop: A0@0 [16][68] (4352) | A1@4352 | B0@8704 (36864) | B1@45568..82432
//  tail:     Ht@0 [256][66] (67584) | W2 half-stage @67584 (32768) -> 100352
//            Ls[64][68] overlays @0 after tail.
// =============================================================================
#define SM_A0  0
#define SM_A1  4352
#define SM_B0  8704
#define SM_B1  45568
#define SM_HT  0
#define SM_W2  67584
#define SM_LS  0
#define SM_TOTAL 100352
#define BROW   2304     // dup-B row stride in bytes (128 cps * 16 + swizzle pads)
#define ASTR   68       // A row stride in floats (272 B, 16B-aligned rows)

__global__ __launch_bounds__(256, 2)
void fused_gating(const float* __restrict__ X,
                  const float* __restrict__ W1,
                  const float* __restrict__ b1,
                  const float* __restrict__ W2,
                  const float* __restrict__ b2,
                  float* __restrict__ out_gates,
                  float* __restrict__ out_logits) {
    extern __shared__ char sm[];
    __shared__ float b1s[256];
    __shared__ float b2s[64];
    __shared__ int   si1[64], si2[64];
    __shared__ float sg1[64], sg2[64];

    const uint32_t sb = smem_u32(sm);
    const int tid  = threadIdx.x;
    const int wid  = tid >> 5, lane = tid & 31;
    const int m0   = blockIdx.x * 64;
    const int wm   = wid & 1;          // token half (32)
    const int wn   = wid >> 1;         // col block (64)
    const int tm   = lane >> 3;        // token group: 8 consecutive tokens
    const int tn   = lane & 7;         // col group: 8 cols

    b1s[tid] = b1[tid];
    if (tid < 64) b2s[tid] = b2[tid];

    // X staging: tok=tid>>2, k4=(tid&3)*4 (one float4/chunk)
    const int xtok = tid >> 2;
    const int xk4  = (tid & 3) * 4;
    // B staging: bk = k-row (0..15), bt = 16-col group
    const int bk   = tid >> 4;
    const int bt   = tid & 15;

    // acc[p][c]: f32x2 tokens (wm*32+tm*8+2p, +1), col wn*64+tn*8+c
    unsigned long long acc[4][8];
#pragma unroll
    for (int p = 0; p < 4; p++)
#pragma unroll
        for (int c = 0; c < 8; c++) acc[p][c] = 0ull;

    float4 xa;
    float4 bw[4];

    // ---- prologue: stage chunk 0 ----
    xa = *(const float4*)(X + (size_t)(m0 + xtok) * D_MODEL + xk4);
#pragma unroll
    for (int i = 0; i < 4; i++)
        bw[i] = *(const float4*)(W1 + (size_t)bk * D_HID + bt * 16 + i * 4);
    {
        float* A = (float*)(sm + SM_A0);
        A[(xk4 + 0) * ASTR + xtok] = xa.x;
        A[(xk4 + 1) * ASTR + xtok] = xa.y;
        A[(xk4 + 2) * ASTR + xtok] = xa.z;
        A[(xk4 + 3) * ASTR + xtok] = xa.w;
        const uint32_t Bb = sb + SM_B0 + bk * BROW;
#pragma unroll
        for (int i = 0; i < 4; i++) {
            int cp = bt * 8 + 2 * i;
            sts_dup4(Bb + boff(cp),      bw[i].x, bw[i].y);
            sts_dup4(Bb + boff(cp) + 16, bw[i].z, bw[i].w);
        }
    }

    const int bb0 = boff(wn * 32 + tn * 4);   // this thread's 64B dup window

    // ---- mainloop: 64 chunks of K=16 ----
    for (int c = 0; c < 64; c++) {
        const int b = c & 1;
        if (c < 63) {
            const int kt = (c + 1) * 16;
            xa = *(const float4*)(X + (size_t)(m0 + xtok) * D_MODEL + kt + xk4);
#pragma unroll
            for (int i = 0; i < 4; i++)
                bw[i] = *(const float4*)(W1 + (size_t)(kt + bk) * D_HID + bt * 16 + i * 4);
        }
        __syncthreads();

        const float* As = (const float*)(sm + (b ? SM_A1 : SM_A0));
        const char*  Bs = sm + (b ? SM_B1 : SM_B0);

#pragma unroll
        for (int k = 0; k < 16; k++) {
            ulonglong2 u0 = *(const ulonglong2*)(As + k * ASTR + wm * 32 + tm * 8);
            ulonglong2 u1 = *(const ulonglong2*)(As + k * ASTR + wm * 32 + tm * 8 + 4);
            const char* Brow = Bs + k * BROW + bb0;
            ulonglong2 w0 = *(const ulonglong2*)(Brow);
            ulonglong2 w1 = *(const ulonglong2*)(Brow + 16);
            ulonglong2 w2 = *(const ulonglong2*)(Brow + 32);
            ulonglong2 w3 = *(const ulonglong2*)(Brow + 48);
            unsigned long long bbv[8] = {w0.x, w0.y, w1.x, w1.y,
                                         w2.x, w2.y, w3.x, w3.y};
#pragma unroll
            for (int cc = 0; cc < 8; cc++) {
                ffma2(acc[0][cc], u0.x, bbv[cc]);
                ffma2(acc[1][cc], u0.y, bbv[cc]);
                ffma2(acc[2][cc], u1.x, bbv[cc]);
                ffma2(acc[3][cc], u1.y, bbv[cc]);
            }
        }
        __syncthreads();
        if (c < 63) {
            float* A = (float*)(sm + (b ? SM_A0 : SM_A1));
            A[(xk4 + 0) * ASTR + xtok] = xa.x;
            A[(xk4 + 1) * ASTR + xtok] = xa.y;
            A[(xk4 + 2) * ASTR + xtok] = xa.z;
            A[(xk4 + 3) * ASTR + xtok] = xa.w;
            const uint32_t Bb = sb + (b ? SM_B0 : SM_B1) + bk * BROW;
#pragma unroll
            for (int i = 0; i < 4; i++) {
                int cp = bt * 8 + 2 * i;
                sts_dup4(Bb + boff(cp),      bw[i].x, bw[i].y);
                sts_dup4(Bb + boff(cp) + 16, bw[i].z, bw[i].w);
            }
        }
    }

    // ---- stage W2 half 0 into dead B region (after final sync) ----
#pragma unroll
    for (int i = 0; i < 8; i++) {
        int q = tid + i * 256;          // 0..2047 float4s: W2 rows 0..127
        cp16(sb + SM_W2 + q * 16, W2 + (size_t)q * 4);
    }
    CP_COMMIT();

    // ---- H = tanh(acc + b1) -> Ht[k][tok] (stride 66) ----
    float* Ht = (float*)(sm + SM_HT);
#pragma unroll
    for (int p = 0; p < 4; p++) {
        int tok0 = wm * 32 + tm * 8 + 2 * p;
#pragma unroll
        for (int cc = 0; cc < 8; cc++) {
            int col = wn * 64 + tn * 8 + cc;
            float2 v = unpack2(acc[p][cc]);
            float2 hv;
            hv.x = tanhf(v.x + b1s[col]);
            hv.y = tanhf(v.y + b1s[col]);
            *(float2*)(Ht + col * 66 + tok0) = hv;
        }
    }
    CP_WAIT0();
    __syncthreads();

    // ---- tail GEMM2: logits = Ht^T @ W2 (two 32KB W2 halves in smem) ----
    const int tg = wid;                 // tokens tg*8 .. +7
    const int ep = lane;                // expert pair: experts 2*ep, 2*ep+1
    const float* Ws = (const float*)(sm + SM_W2);

    unsigned long long acc2[4][2];
#pragma unroll
    for (int tp = 0; tp < 4; tp++) { acc2[tp][0] = 0ull; acc2[tp][1] = 0ull; }

#pragma unroll
    for (int half = 0; half < 2; half++) {
#pragma unroll 8
        for (int kk = 0; kk < 128; kk++) {
            const int k = half * 128 + kk;
            unsigned long long w = *(const unsigned long long*)(Ws + kk * 64 + ep * 2);
            float2 wf = unpack2(w);
            unsigned long long w0 = pack2(wf.x, wf.x);
            unsigned long long w1 = pack2(wf.y, wf.y);
#pragma unroll
            for (int tp = 0; tp < 4; tp++) {
                unsigned long long hh = *(const unsigned long long*)
                                        (Ht + k * 66 + tg * 8 + tp * 2);
                ffma2(acc2[tp][0], hh, w0);
                ffma2(acc2[tp][1], hh, w1);
            }
        }
        if (half == 0) {
            __syncthreads();            // all done with W2 half 0
#pragma unroll
            for (int i = 0; i < 8; i++) {
                int q = tid + i * 256;
                cp16(sb + SM_W2 + q * 16, W2 + (size_t)(2048 + q) * 4);
            }
            CP_COMMIT();
            CP_WAIT0();
            __syncthreads();
        }
    }
    __syncthreads();                    // all Ht reads done; overlay Ls

    // ---- stage logits (+b2) into Ls[64][68] ----
    float* Ls = (float*)(sm + SM_LS);
#pragma unroll
    for (int tp = 0; tp < 4; tp++) {
        int t0 = tg * 8 + tp * 2;
        int e0 = ep * 2;
        float2 v0 = unpack2(acc2[tp][0]);
        float2 v1 = unpack2(acc2[tp][1]);
        Ls[t0 * 68 + e0]           = v0.x + b2s[e0];
        Ls[(t0 + 1) * 68 + e0]     = v0.y + b2s[e0];
        Ls[t0 * 68 + e0 + 1]       = v1.x + b2s[e0 + 1];
        Ls[(t0 + 1) * 68 + e0 + 1] = v1.y + b2s[e0 + 1];
    }
    __syncthreads();

    // ---- per-token top-2 + softmax-of-2 ----
    if (tid < 64) {
        const float* Lrow = Ls + tid * 68;
        float v1 = -INFINITY, v2 = -INFINITY;
        int i1 = 0, i2 = 0;
#pragma unroll
        for (int e = 0; e < N_EXP; e++) {
            float v = Lrow[e];
            if (v > v1)      { v2 = v1; i2 = i1; v1 = v; i1 = e; }
            else if (v > v2) { v2 = v; i2 = e; }
        }
        float e2  = __expf(v2 - v1);
        float inv = 1.0f / (1.0f + e2);
        si1[tid] = i1; si2[tid] = i2;
        sg1[tid] = inv; sg2[tid] = e2 * inv;
    }
    __syncthreads();

    // ---- coalesced writeback: logits + dense gates ----
#pragma unroll
    for (int i = 0; i < 4; i++) {
        int f = tid + i * 256;                // 0..1023
        int row = f >> 4, c4 = (f & 15) * 4;
        float4 lv = *(const float4*)(Ls + row * 68 + c4);
        int i1 = si1[row], i2 = si2[row];
        float g1 = sg1[row], g2 = sg2[row];
        float4 gv;
        gv.x = (c4 + 0 == i1) ? g1 : ((c4 + 0 == i2) ? g2 : 0.0f);
        gv.y = (c4 + 1 == i1) ? g1 : ((c4 + 1 == i2) ? g2 : 0.0f);
        gv.z = (c4 + 2 == i1) ? g1 : ((c4 + 2 == i2) ? g2 : 0.0f);
        gv.w = (c4 + 3 == i1) ? g1 : ((c4 + 3 == i2) ? g2 : 0.0f);
        const size_t base = (size_t)(m0 + row) * N_EXP + c4;
        *(float4*)(out_logits + base) = lv;
        *(float4*)(out_gates  + base) = gv;
    }
}

// =============================================================================
extern "C" void kernel_launch(void* const* d_in, const int* in_sizes, int n_in,
                              void* d_out, int out_size) {
    const float* x  = (const float*)d_in[0];   // [4,4096,1024]
    const float* W1 = (const float*)d_in[1];   // [1024,256]
    const float* b1 = (const float*)d_in[2];   // [256]
    const float* W2 = (const float*)d_in[3];   // [256,64]
    const float* b2 = (const float*)d_in[4];   // [64]

    float* out        = (float*)d_out;
    float* out_gates  = out;
    float* out_logits = out + (size_t)out_size / 2;

    cudaFuncSetAttribute(fused_gating, cudaFuncAttributeMaxDynamicSharedMemorySize,
                         SM_TOTAL);
    fused_gating<<<NTOK / 64, 256, SM_TOTAL>>>(x, W1, b1, W2, b2,
                                               out_gates, out_logits);
}

// round 16
// speedup vs baseline: 1.2388x; 1.2388x over previous
#include <cuda_runtime.h>
#include <math.h>
#include <stdint.h>

#define D_MODEL 1024
#define D_HID   256
#define N_EXP   64
#define NTOK    16384

// ---------------- packed fp32x2 helpers (FFMA2 path) ----------------
__device__ __forceinline__ unsigned long long pack2(float lo, float hi) {
    unsigned long long r;
    asm("mov.b64 %0, {%1, %2};" : "=l"(r) : "f"(lo), "f"(hi));
    return r;
}
__device__ __forceinline__ void ffma2(unsigned long long& d,
                                      unsigned long long a,
                                      unsigned long long b) {
    asm("fma.rn.f32x2 %0, %1, %2, %0;" : "+l"(d) : "l"(a), "l"(b));
}
__device__ __forceinline__ float2 unpack2(unsigned long long v) {
    float2 f;
    asm("mov.b64 {%0, %1}, %2;" : "=f"(f.x), "=f"(f.y) : "l"(v));
    return f;
}
__device__ __forceinline__ void cp16(uint32_t saddr, const void* gsrc) {
    asm volatile("cp.async.cg.shared.global [%0], [%1], 16;" :: "r"(saddr), "l"(gsrc) : "memory");
}
#define CP_COMMIT() asm volatile("cp.async.commit_group;" ::: "memory")
#define CP_WAIT0()  asm volatile("cp.async.wait_group 0;" ::: "memory")
#define CP_WAIT1()  asm volatile("cp.async.wait_group 1;" ::: "memory")

__device__ __forceinline__ uint32_t smem_u32(const void* p) {
    uint32_t a;
    asm("{ .reg .u64 t; cvta.to.shared.u64 t, %1; cvt.u32.u64 %0, t; }" : "=r"(a) : "l"(p));
    return a;
}

// =============================================================================
// Fully fused gating network, pure fp32 (exact):
//   H = tanh(X@W1+b1) -> smem Ht[k][tok]; logits = H@W2+b2; top-2 softmax.
// CTA 256 thr, M=64 tokens (grid 256), N=256, BK=32 (32 chunks, 64 syncs),
// occ 2, 8x8 thread tile, broadcast-dedup smem reads (R12 shape).
// Inner loop/warp/k: A 2xLDS.128 (aligned stride-68 rows) +
//                    B 2xLDS.128 (broadcast) + 8 packs + 32 FFMA2.
//
// Dynamic smem (bytes), temporally-disjoint overlays:
//  mainloop: A0@0 [32][68] (8704) | A1@8704 | B0@17408 [32][260] (33280)
//            | B1@50688 .. 83968
//  tail:     Ht@0 [256][66] (67584) | W2 half-stage @67584 (32768) -> 100352
//            Ls[64][68] overlays @0 after tail.
// =============================================================================
#define SM_A0  0
#define SM_A1  8704
#define SM_B0  17408
#define SM_B1  50688
#define SM_HT  0
#define SM_W2  67584
#define SM_LS  0
#define SM_TOTAL 100352
#define ASTR   68       // A row stride in floats (272 B: LDS.128-aligned rows)
#define BSTR   260      // B row stride in floats (1040 B, R12-measured layout)

__global__ __launch_bounds__(256, 2)
void fused_gating(const float* __restrict__ X,
                  const float* __restrict__ W1,
                  const float* __restrict__ b1,
                  const float* __restrict__ W2,
                  const float* __restrict__ b2,
                  float* __restrict__ out_gates,
                  float* __restrict__ out_logits) {
    extern __shared__ char sm[];
    __shared__ float b1s[256];
    __shared__ float b2s[64];
    __shared__ int   si1[64], si2[64];
    __shared__ float sg1[64], sg2[64];

    const uint32_t sb = smem_u32(sm);
    const int tid  = threadIdx.x;
    const int wid  = tid >> 5, lane = tid & 31;
    const int m0   = blockIdx.x * 64;
    const int wm   = wid & 1;          // token half (32)
    const int wn   = wid >> 1;         // col block (64)
    const int tm   = lane >> 3;        // token group: 8 consecutive tokens
    const int tn   = lane & 7;         // col group: 8 cols

    b1s[tid] = b1[tid];
    if (tid < 64) b2s[tid] = b2[tid];

    // X staging: tok=tid>>2, cols xk4 and xk4+16 (two float4s per chunk)
    const int xtok = tid >> 2;
    const int xk4  = (tid & 3) * 4;

    // acc[p][c]: f32x2 tokens (wm*32+tm*8+2p, +1), col wn*64+tn*8+c
    unsigned long long acc[4][8];
#pragma unroll
    for (int p = 0; p < 4; p++)
#pragma unroll
        for (int c = 0; c < 8; c++) acc[p][c] = 0ull;

    float4 xa0, xa1;

    // ---- prologue: stage chunk 0 ----
    xa0 = *(const float4*)(X + (size_t)(m0 + xtok) * D_MODEL + xk4);
    xa1 = *(const float4*)(X + (size_t)(m0 + xtok) * D_MODEL + xk4 + 16);
    {
        float* A = (float*)(sm + SM_A0);
        A[(xk4 + 0) * ASTR + xtok]  = xa0.x;
        A[(xk4 + 1) * ASTR + xtok]  = xa0.y;
        A[(xk4 + 2) * ASTR + xtok]  = xa0.z;
        A[(xk4 + 3) * ASTR + xtok]  = xa0.w;
        A[(xk4 + 16) * ASTR + xtok] = xa1.x;
        A[(xk4 + 17) * ASTR + xtok] = xa1.y;
        A[(xk4 + 18) * ASTR + xtok] = xa1.z;
        A[(xk4 + 19) * ASTR + xtok] = xa1.w;
    }
#pragma unroll
    for (int i = 0; i < 8; i++) {
        int q = tid + i * 256;              // 0..2047
        int krow = q >> 6, c16 = q & 63;    // 32 rows x 64 float4s
        cp16(sb + SM_B0 + krow * (BSTR * 4) + c16 * 16,
             W1 + (size_t)krow * D_HID + c16 * 4);
    }
    CP_COMMIT();

    // ---- mainloop: 32 chunks of K=32 ----
    for (int c = 0; c < 32; c++) {
        const int b = c & 1;
        if (c < 31) {
            const int kt = (c + 1) * 32;
            xa0 = *(const float4*)(X + (size_t)(m0 + xtok) * D_MODEL + kt + xk4);
            xa1 = *(const float4*)(X + (size_t)(m0 + xtok) * D_MODEL + kt + xk4 + 16);
            const uint32_t Bb = sb + (b ? SM_B0 : SM_B1);
#pragma unroll
            for (int i = 0; i < 8; i++) {
                int q = tid + i * 256;
                int krow = q >> 6, c16 = q & 63;
                cp16(Bb + krow * (BSTR * 4) + c16 * 16,
                     W1 + (size_t)(kt + krow) * D_HID + c16 * 4);
            }
            CP_COMMIT();
            CP_WAIT1();
        } else {
            CP_WAIT0();
        }
        __syncthreads();

        const float* As = (const float*)(sm + (b ? SM_A1 : SM_A0));
        const float* Bs = (const float*)(sm + (b ? SM_B1 : SM_B0));

#pragma unroll
        for (int k = 0; k < 32; k++) {
            ulonglong2 u0 = *(const ulonglong2*)(As + k * ASTR + wm * 32 + tm * 8);
            ulonglong2 u1 = *(const ulonglong2*)(As + k * ASTR + wm * 32 + tm * 8 + 4);
            float4 bv0 = *(const float4*)(Bs + k * BSTR + wn * 64 + tn * 8);
            float4 bv1 = *(const float4*)(Bs + k * BSTR + wn * 64 + tn * 8 + 4);
            unsigned long long bb[8];
            bb[0] = pack2(bv0.x, bv0.x); bb[1] = pack2(bv0.y, bv0.y);
            bb[2] = pack2(bv0.z, bv0.z); bb[3] = pack2(bv0.w, bv0.w);
            bb[4] = pack2(bv1.x, bv1.x); bb[5] = pack2(bv1.y, bv1.y);
            bb[6] = pack2(bv1.z, bv1.z); bb[7] = pack2(bv1.w, bv1.w);
#pragma unroll
            for (int cc = 0; cc < 8; cc++) {
                ffma2(acc[0][cc], u0.x, bb[cc]);
                ffma2(acc[1][cc], u0.y, bb[cc]);
                ffma2(acc[2][cc], u1.x, bb[cc]);
                ffma2(acc[3][cc], u1.y, bb[cc]);
            }
        }
        __syncthreads();
        if (c < 31) {
            float* A = (float*)(sm + (b ? SM_A0 : SM_A1));
            A[(xk4 + 0) * ASTR + xtok]  = xa0.x;
            A[(xk4 + 1) * ASTR + xtok]  = xa0.y;
            A[(xk4 + 2) * ASTR + xtok]  = xa0.z;
            A[(xk4 + 3) * ASTR + xtok]  = xa0.w;
            A[(xk4 + 16) * ASTR + xtok] = xa1.x;
            A[(xk4 + 17) * ASTR + xtok] = xa1.y;
            A[(xk4 + 18) * ASTR + xtok] = xa1.z;
            A[(xk4 + 19) * ASTR + xtok] = xa1.w;
        }
    }

    // ---- stage W2 half 0 into dead B region (after final sync) ----
#pragma unroll
    for (int i = 0; i < 8; i++) {
        int q = tid + i * 256;          // 0..2047 float4s: W2 rows 0..127
        cp16(sb + SM_W2 + q * 16, W2 + (size_t)q * 4);
    }
    CP_COMMIT();

    // ---- H = tanh(acc + b1) -> Ht[k][tok] (stride 66) ----
    float* Ht = (float*)(sm + SM_HT);
#pragma unroll
    for (int p = 0; p < 4; p++) {
        int tok0 = wm * 32 + tm * 8 + 2 * p;
#pragma unroll
        for (int cc = 0; cc < 8; cc++) {
            int col = wn * 64 + tn * 8 + cc;
            float2 v = unpack2(acc[p][cc]);
            float2 hv;
            hv.x = tanhf(v.x + b1s[col]);
            hv.y = tanhf(v.y + b1s[col]);
            *(float2*)(Ht + col * 66 + tok0) = hv;
        }
    }
    CP_WAIT0();
    __syncthreads();

    // ---- tail GEMM2: logits = Ht^T @ W2 (two 32KB W2 halves in smem) ----
    const int tg = wid;                 // tokens tg*8 .. +7
    const int ep = lane;                // expert pair: experts 2*ep, 2*ep+1
    const float* Ws = (const float*)(sm + SM_W2);

    unsigned long long acc2[4][2];
#pragma unroll
    for (int tp = 0; tp < 4; tp++) { acc2[tp][0] = 0ull; acc2[tp][1] = 0ull; }

#pragma unroll
    for (int half = 0; half < 2; half++) {
#pragma unroll 8
        for (int kk = 0; kk < 128; kk++) {
            const int k = half * 128 + kk;
            unsigned long long w = *(const unsigned long long*)(Ws + kk * 64 + ep * 2);
            float2 wf = unpack2(w);
            unsigned long long w0 = pack2(wf.x, wf.x);
            unsigned long long w1 = pack2(wf.y, wf.y);
#pragma unroll
            for (int tp = 0; tp < 4; tp++) {
                unsigned long long hh = *(const unsigned long long*)
                                        (Ht + k * 66 + tg * 8 + tp * 2);
                ffma2(acc2[tp][0], hh, w0);
                ffma2(acc2[tp][1], hh, w1);
            }
        }
        if (half == 0) {
            __syncthreads();            // all done with W2 half 0
#pragma unroll
            for (int i = 0; i < 8; i++) {
                int q = tid + i * 256;
                cp16(sb + SM_W2 + q * 16, W2 + (size_t)(2048 + q) * 4);
            }
            CP_COMMIT();
            CP_WAIT0();
            __syncthreads();
        }
    }
    __syncthreads();                    // all Ht reads done; overlay Ls

    // ---- stage logits (+b2) into Ls[64][68] ----
    float* Ls = (float*)(sm + SM_LS);
#pragma unroll
    for (int tp = 0; tp < 4; tp++) {
        int t0 = tg * 8 + tp * 2;
        int e0 = ep * 2;
        float2 v0 = unpack2(acc2[tp][0]);
        float2 v1 = unpack2(acc2[tp][1]);
        Ls[t0 * 68 + e0]           = v0.x + b2s[e0];
        Ls[(t0 + 1) * 68 + e0]     = v0.y + b2s[e0];
        Ls[t0 * 68 + e0 + 1]       = v1.x + b2s[e0 + 1];
        Ls[(t0 + 1) * 68 + e0 + 1] = v1.y + b2s[e0 + 1];
    }
    __syncthreads();

    // ---- per-token top-2 + softmax-of-2 ----
    if (tid < 64) {
        const float* Lrow = Ls + tid * 68;
        float v1 = -INFINITY, v2 = -INFINITY;
        int i1 = 0, i2 = 0;
#pragma unroll
        for (int e = 0; e < N_EXP; e++) {
            float v = Lrow[e];
            if (v > v1)      { v2 = v1; i2 = i1; v1 = v; i1 = e; }
            else if (v > v2) { v2 = v; i2 = e; }
        }
        float e2  = __expf(v2 - v1);
        float inv = 1.0f / (1.0f + e2);
        si1[tid] = i1; si2[tid] = i2;
        sg1[tid] = inv; sg2[tid] = e2 * inv;
    }
    __syncthreads();

    // ---- coalesced writeback: logits + dense gates ----
#pragma unroll
    for (int i = 0; i < 4; i++) {
        int f = tid + i * 256;                // 0..1023
        int row = f >> 4, c4 = (f & 15) * 4;
        float4 lv = *(const float4*)(Ls + row * 68 + c4);
        int i1 = si1[row], i2 = si2[row];
        float g1 = sg1[row], g2 = sg2[row];
        float4 gv;
        gv.x = (c4 + 0 == i1) ? g1 : ((c4 + 0 == i2) ? g2 : 0.0f);
        gv.y = (c4 + 1 == i1) ? g1 : ((c4 + 1 == i2) ? g2 : 0.0f);
        gv.z = (c4 + 2 == i1) ? g1 : ((c4 + 2 == i2) ? g2 : 0.0f);
        gv.w = (c4 + 3 == i1) ? g1 : ((c4 + 3 == i2) ? g2 : 0.0f);
        const size_t base = (size_t)(m0 + row) * N_EXP + c4;
        *(float4*)(out_logits + base) = lv;
        *(float4*)(out_gates  + base) = gv;
    }
}

// =============================================================================
extern "C" void kernel_launch(void* const* d_in, const int* in_sizes, int n_in,
                              void* d_out, int out_size) {
    const float* x  = (const float*)d_in[0];   // [4,4096,1024]
    const float* W1 = (const float*)d_in[1];   // [1024,256]
    const float* b1 = (const float*)d_in[2];   // [256]
    const float* W2 = (const float*)d_in[3];   // [256,64]
    const float* b2 = (const float*)d_in[4];   // [64]

    float* out        = (float*)d_out;
    float* out_gates  = out;
    float* out_logits = out + (size_t)out_size / 2;

    cudaFuncSetAttribute(fused_gating, cudaFuncAttributeMaxDynamicSharedMemorySize,
                         SM_TOTAL);
    fused_gating<<<NTOK / 64, 256, SM_TOTAL>>>(x, W1, b1, W2, b2,
                                               out_gates, out_logits);
}